// round 14
// baseline (speedup 1.0000x reference)
#include <cuda_runtime.h>
#include <cstdint>

// LaneAttention, sm_103: merged projection kernel (KV persistent + Q tiles,
// register-prefetch pipelined, mma.sync tf32 3-pass) + fused attention+Y
// kernel (fp32/f32x2, Y = O @ Wc^T + residual done in-SMEM).

#define TT    30
#define FF    128
#define LL    64
#define LFN   64
#define THN   20
#define NUNIT 2048
#define NROWQ (TT*NUNIT)   // 61440

#define KV_BLOCKS (2 * 296)          // 592
#define Q_BLOCKS  (NROWQ / 128)      // 480
#define PROJ_BLOCKS (KV_BLOCKS + Q_BLOCKS)

typedef unsigned long long u64;

// ---------------- scratch ----------------
__device__ float g_K[NUNIT * 128 * 64];
__device__ float g_V[NUNIT * 128 * 64];
__device__ float g_Q[NROWQ * 128];

// ---------------- tf32 helpers ----------------
__device__ __forceinline__ uint32_t to_tf32(float x) {
    uint32_t r;
    asm("cvt.rna.tf32.f32 %0, %1;" : "=r"(r) : "f"(x));
    return r;
}
__device__ __forceinline__ void mma_tf32(float* d, const uint32_t* a,
                                         uint32_t b0, uint32_t b1) {
    asm volatile(
        "mma.sync.aligned.m16n8k8.row.col.f32.tf32.tf32.f32 "
        "{%0,%1,%2,%3}, {%4,%5,%6,%7}, {%8,%9}, {%0,%1,%2,%3};"
        : "+f"(d[0]), "+f"(d[1]), "+f"(d[2]), "+f"(d[3])
        : "r"(a[0]), "r"(a[1]), "r"(a[2]), "r"(a[3]), "r"(b0), "r"(b1));
}
__device__ __forceinline__ uint32_t f2u(float x) { return __float_as_uint(x); }

__device__ __forceinline__ void stage64(float* hi, float* lo,
                                        const float* __restrict__ src,
                                        int ld, int tid)
{
    for (int i4 = tid; i4 < 128 * 16; i4 += 256) {
        int r = i4 >> 4, k = (i4 & 15) * 4;
        float4 v = *(const float4*)&src[(size_t)r * ld + k];
        uint32_t hx = to_tf32(v.x), hy = to_tf32(v.y),
                 hz = to_tf32(v.z), hw = to_tf32(v.w);
        int o = r * 68 + k;
        *(uint4*)&hi[o] = make_uint4(hx, hy, hz, hw);
        *(uint4*)&lo[o] = make_uint4(to_tf32(v.x - __uint_as_float(hx)),
                                     to_tf32(v.y - __uint_as_float(hy)),
                                     to_tf32(v.z - __uint_as_float(hz)),
                                     to_tf32(v.w - __uint_as_float(hw)));
    }
}
__device__ __forceinline__ void stage32(float* hi, float* lo,
                                        const float* __restrict__ src,
                                        int ld, int tid)
{
    for (int i4 = tid; i4 < 128 * 8; i4 += 256) {
        int r = i4 >> 3, k = (i4 & 7) * 4;
        float4 v = *(const float4*)&src[(size_t)r * ld + k];
        uint32_t hx = to_tf32(v.x), hy = to_tf32(v.y),
                 hz = to_tf32(v.z), hw = to_tf32(v.w);
        int o = r * 36 + k;
        *(uint4*)&hi[o] = make_uint4(hx, hy, hz, hw);
        *(uint4*)&lo[o] = make_uint4(to_tf32(v.x - __uint_as_float(hx)),
                                     to_tf32(v.y - __uint_as_float(hy)),
                                     to_tf32(v.z - __uint_as_float(hz)),
                                     to_tf32(v.w - __uint_as_float(hw)));
    }
}
__device__ __forceinline__ void prefetch32(float4 pf[4],
                                           const float* __restrict__ src,
                                           int ld, int tid)
{
    #pragma unroll
    for (int j = 0; j < 4; j++) {
        int i4 = tid + j * 256;
        int r = i4 >> 3, k = (i4 & 7) * 4;
        pf[j] = *(const float4*)&src[(size_t)r * ld + k];
    }
}
__device__ __forceinline__ void commit32(float* hi, float* lo,
                                         const float4 pf[4], int tid)
{
    #pragma unroll
    for (int j = 0; j < 4; j++) {
        int i4 = tid + j * 256;
        int r = i4 >> 3, k = (i4 & 7) * 4;
        float4 v = pf[j];
        uint32_t hx = to_tf32(v.x), hy = to_tf32(v.y),
                 hz = to_tf32(v.z), hw = to_tf32(v.w);
        int o = r * 36 + k;
        *(uint4*)&hi[o] = make_uint4(hx, hy, hz, hw);
        *(uint4*)&lo[o] = make_uint4(to_tf32(v.x - __uint_as_float(hx)),
                                     to_tf32(v.y - __uint_as_float(hy)),
                                     to_tf32(v.z - __uint_as_float(hz)),
                                     to_tf32(v.w - __uint_as_float(hw)));
    }
}

__device__ __forceinline__ void mma_k32(const float* aH, const float* aL, int lda,
                                        const float* bH, const float* bL, int ldb,
                                        float d[2][8][4],
                                        int wm, int wn, int qr, int qc)
{
    #pragma unroll 1
    for (int ks = 0; ks < 4; ks++) {
        const int kb = ks * 8 + qc;
        uint32_t ah[2][4], al[2][4];
        #pragma unroll
        for (int i = 0; i < 2; i++) {
            int r0 = (wm + i * 16 + qr) * lda;
            ah[i][0] = f2u(aH[r0 + kb]);
            ah[i][1] = f2u(aH[r0 + 8 * lda + kb]);
            ah[i][2] = f2u(aH[r0 + kb + 4]);
            ah[i][3] = f2u(aH[r0 + 8 * lda + kb + 4]);
            al[i][0] = f2u(aL[r0 + kb]);
            al[i][1] = f2u(aL[r0 + 8 * lda + kb]);
            al[i][2] = f2u(aL[r0 + kb + 4]);
            al[i][3] = f2u(aL[r0 + 8 * lda + kb + 4]);
        }
        #pragma unroll
        for (int j = 0; j < 8; j++) {
            int nb = (wn + j * 8 + qr) * ldb;
            uint32_t bh0 = f2u(bH[nb + kb]);
            uint32_t bh1 = f2u(bH[nb + kb + 4]);
            uint32_t bl0 = f2u(bL[nb + kb]);
            uint32_t bl1 = f2u(bL[nb + kb + 4]);
            #pragma unroll
            for (int i = 0; i < 2; i++) {
                mma_tf32(d[i][j], ah[i], bh0, bh1);
                mma_tf32(d[i][j], ah[i], bl0, bl1);
                mma_tf32(d[i][j], al[i], bh0, bh1);
            }
        }
    }
}

// ================= merged projection kernel =================
#define PROJ_SMEM (26624 * 4)   // 106496 B -> 2 CTAs/SM for both roles

__global__ void __launch_bounds__(256, 2)
proj_gemm(const float* __restrict__ lanes, const float* __restrict__ Wk,
          const float* __restrict__ Wv, const float* __restrict__ veh,
          const float* __restrict__ Wq)
{
    extern __shared__ float sm[];
    const int tid = threadIdx.x, wid = tid >> 5, lane = tid & 31;
    const int qr = lane >> 2, qc = lane & 3;
    const int wm = (wid >> 1) * 32, wn = (wid & 1) * 64;

    if (blockIdx.x < KV_BLOCKS) {
        float* AH = sm;
        float* AL = sm + 8704;
        float* BH = sm + 17408;
        float* BL = sm + 22016;
        const int nt = blockIdx.x / 296, b2 = blockIdx.x % 296;

        stage64(AH, AL, nt ? Wv : Wk, 64, tid);
        float* dst = nt ? g_V : g_K;

        float4 pf[4];
        prefetch32(pf, lanes + (size_t)b2 * 8192, 64, tid);

        #pragma unroll 1
        for (int ntile = b2; ntile < 1024; ntile += 296) {
            float d[2][8][4];
            #pragma unroll
            for (int i = 0; i < 2; i++)
                #pragma unroll
                for (int j = 0; j < 8; j++)
                    d[i][j][0] = d[i][j][1] = d[i][j][2] = d[i][j][3] = 0.f;

            #pragma unroll 1
            for (int ch = 0; ch < 2; ch++) {
                __syncthreads();
                commit32(BH, BL, pf, tid);
                __syncthreads();
                if (ch == 0) {
                    prefetch32(pf, lanes + (size_t)ntile * 8192 + 32, 64, tid);
                } else if (ntile + 296 < 1024) {
                    prefetch32(pf, lanes + (size_t)(ntile + 296) * 8192, 64, tid);
                }
                mma_k32(AH + ch * 32, AL + ch * 32, 68, BH, BL, 36,
                        d, wm, wn, qr, qc);
            }

            const int u0 = ntile * 2;
            #pragma unroll
            for (int i = 0; i < 2; i++)
                #pragma unroll
                for (int j = 0; j < 8; j++) {
                    int g = wm + i * 16 + qr;
                    int c = wn + j * 8 + 2 * qc;
                    int u = u0 + (c >> 6), l = c & 63;
                    *(float2*)&dst[(size_t)u * 8192 + g * 64 + l] =
                        make_float2(d[i][j][0], d[i][j][1]);
                    *(float2*)&dst[(size_t)u * 8192 + (g + 8) * 64 + l] =
                        make_float2(d[i][j][2], d[i][j][3]);
                }
        }
    } else {
        float* AH = sm;
        float* AL = sm + 4608;
        float* BH = sm + 9216;
        float* BL = sm + 13824;
        const int m0 = (blockIdx.x - KV_BLOCKS) * 128;

        float d[2][8][4];
        #pragma unroll
        for (int i = 0; i < 2; i++)
            #pragma unroll
            for (int j = 0; j < 8; j++)
                d[i][j][0] = d[i][j][1] = d[i][j][2] = d[i][j][3] = 0.f;

        float4 pf[4];
        prefetch32(pf, veh + (size_t)m0 * 128, 128, tid);

        #pragma unroll 1
        for (int ch = 0; ch < 4; ch++) {
            commit32(AH, AL, pf, tid);
            stage32(BH, BL, Wq + ch * 32, 128, tid);
            __syncthreads();
            if (ch < 3)
                prefetch32(pf, veh + (size_t)m0 * 128 + (ch + 1) * 32, 128, tid);
            mma_k32(AH, AL, 36, BH, BL, 36, d, wm, wn, qr, qc);
            __syncthreads();
        }

        #pragma unroll
        for (int i = 0; i < 2; i++)
            #pragma unroll
            for (int j = 0; j < 8; j++) {
                int r = m0 + wm + i * 16 + qr, c = wn + j * 8 + 2 * qc;
                *(float2*)&g_Q[(size_t)r * 128 + c]       = make_float2(d[i][j][0], d[i][j][1]);
                *(float2*)&g_Q[(size_t)(r + 8) * 128 + c] = make_float2(d[i][j][2], d[i][j][3]);
            }
    }
}

// ================= fused attention + Y kernel (fp32, per-unit) =================
// SMEM layout (floats):
//   AKT @0     : Kt[128][65] (scores) -> O[30][132] (after PV)
//   AVT @8320  : Vt[128][65] (PV)     -> Wc quarter pair tiles 2x[32][130]=8320
//   AQ  @16640 : Q[30][132]
//   AP  @20600 : P[30][256]           -> Y reduce partials PB[30][64] u64
#define AKT_OFF 0
#define AO_OFF  0
#define AVT_OFF 8320
#define AWC_OFF 8320
#define AQ_OFF  16640
#define AP_OFF  20600
#define APB_OFF 20600
#define A_SMEM_FLOATS 28280   // 113120 B -> 2 CTAs/SM

__device__ __forceinline__ u64 ffma2(u64 a, u64 b, u64 c) {
    u64 d;
    asm("fma.rn.f32x2 %0, %1, %2, %3;" : "=l"(d) : "l"(a), "l"(b), "l"(c));
    return d;
}
__device__ __forceinline__ u64 addf2(u64 a, u64 b) {
    u64 d;
    asm("add.rn.f32x2 %0, %1, %2;" : "=l"(d) : "l"(a), "l"(b));
    return d;
}
__device__ __forceinline__ u64 dup2(float x) {
    u64 d; asm("mov.b64 %0, {%1, %1};" : "=l"(d) : "f"(x)); return d;
}
__device__ __forceinline__ u64 pack2(float lo, float hi) {
    u64 d; asm("mov.b64 %0, {%1, %2};" : "=l"(d) : "f"(lo), "f"(hi)); return d;
}
__device__ __forceinline__ float2 unpack2(u64 a) {
    float2 r; asm("mov.b64 {%0, %1}, %2;" : "=f"(r.x), "=f"(r.y) : "l"(a)); return r;
}

// Stage Wc quarter: two transposed [32][130] tiles at AWC (+0, +4160).
// tile 0 -> f in [stage*32, +32); tile 1 -> f in [64+stage*32, +32).
__device__ __forceinline__ void load_wc2(float* sm, const float* Wsrc,
                                         int stage, int tid) {
    for (int idx = tid; idx < 8192; idx += 512) {
        int tile = idx >> 12;
        int rem  = idx & 4095;
        int g    = rem >> 5;
        int fi   = rem & 31;
        sm[AWC_OFF + tile * 4160 + fi * 130 + g] =
            Wsrc[g * FF + tile * 64 + stage * 32 + fi];
    }
}

__global__ void __launch_bounds__(512, 2)
attn_y_kernel(const int* __restrict__ maskl, const float* __restrict__ Wc,
              const float* __restrict__ veh, float* __restrict__ out)
{
    extern __shared__ float sm[];
    const int tid  = threadIdx.x;
    const int w    = tid >> 5;
    const int lane = tid & 31;
    const int bid  = blockIdx.x;
    const int ah   = w & 3;     // head (attn phases)
    const int atw  = w >> 2;    // t-group of 8 (attn phases)
    // Y-phase warp roles
    const int fh   = w >> 3;          // f-half
    const int gsub = (w >> 2) & 1;    // g 64-half
    const int ytw  = w & 3;           // t-group of 8
    const int gp   = 2 * lane + 64 * gsub;

    int mi0 = 0, mi1 = 0;
    #pragma unroll
    for (int th = 0; th < THN; th++) {
        const int* mp = maskl + (size_t)(th * NUNIT + bid) * LL;
        mi0 |= mp[lane];
        mi1 |= mp[lane + 32];
    }
    const bool km0 = (mi0 != 0), km1 = (mi1 != 0);

    // ---- stage Kt, Vt, Q ----
    {
        const float* kp = g_K + (size_t)bid * 8192;
        const float* vp = g_V + (size_t)bid * 8192;
        for (int idx = tid; idx < 8192; idx += 512) {
            int g = idx >> 6, l = idx & 63;
            sm[AKT_OFF + g * 65 + l] = kp[idx];
            sm[AVT_OFF + g * 65 + l] = vp[idx];
        }
        for (int idx = tid; idx < TT * FF; idx += 512) {
            int t = idx >> 7, g = idx & 127;
            sm[AQ_OFF + t * 132 + g] = g_Q[(size_t)(t * NUNIT + bid) * 128 + g];
        }
    }
    __syncthreads();

    // ---- scores + softmax -> P ----
    {
        const int gb = ah * 32;
        u64 acc[8] = {0,0,0,0,0,0,0,0};
        #pragma unroll 2
        for (int d = 0; d < 32; d += 4) {
            u64 kk[4];
            #pragma unroll
            for (int j = 0; j < 4; j++) {
                float k0 = sm[AKT_OFF + (gb + d + j) * 65 + lane];
                float k1 = sm[AKT_OFF + (gb + d + j) * 65 + lane + 32];
                kk[j] = pack2(k0, k1);
            }
            #pragma unroll
            for (int it = 0; it < 8; it++) {
                int tr = atw * 8 + it; tr = tr < TT ? tr : (TT - 1);
                float4 q = *(const float4*)&sm[AQ_OFF + tr * 132 + gb + d];
                acc[it] = ffma2(dup2(q.x), kk[0], acc[it]);
                acc[it] = ffma2(dup2(q.y), kk[1], acc[it]);
                acc[it] = ffma2(dup2(q.z), kk[2], acc[it]);
                acc[it] = ffma2(dup2(q.w), kk[3], acc[it]);
            }
        }
        const float scale = 0.17677669529663687f;
        #pragma unroll
        for (int it = 0; it < 8; it++) {
            int t = atw * 8 + it;
            if (t >= TT) break;
            float2 sc = unpack2(acc[it]);
            float s0 = km0 ? sc.x * scale : -1e9f;
            float s1 = km1 ? sc.y * scale : -1e9f;
            float m = fmaxf(s0, s1);
            #pragma unroll
            for (int o = 16; o; o >>= 1) m = fmaxf(m, __shfl_xor_sync(0xffffffffu, m, o));
            float e0 = __expf(s0 - m), e1 = __expf(s1 - m);
            float ss = e0 + e1;
            #pragma unroll
            for (int o = 16; o; o >>= 1) ss += __shfl_xor_sync(0xffffffffu, ss, o);
            float inv = 1.0f / ss;
            sm[AP_OFF + t * 256 + ah * 64 + lane]      = e0 * inv;
            sm[AP_OFF + t * 256 + ah * 64 + lane + 32] = e1 * inv;
        }
    }
    __syncthreads();   // Kt now dead -> O overlays it

    // ---- O = P @ V -> O in SMEM (overlay Kt) ----
    {
        const int gb = ah * 32;
        const int vrow = AVT_OFF + (gb + lane) * 65;
        float oacc[8] = {0,0,0,0,0,0,0,0};
        #pragma unroll 2
        for (int l = 0; l < LL; l += 4) {
            float v0 = sm[vrow + l + 0];
            float v1 = sm[vrow + l + 1];
            float v2 = sm[vrow + l + 2];
            float v3 = sm[vrow + l + 3];
            #pragma unroll
            for (int it = 0; it < 8; it++) {
                int tr = atw * 8 + it; tr = tr < TT ? tr : (TT - 1);
                float4 p = *(const float4*)&sm[AP_OFF + tr * 256 + ah * 64 + l];
                oacc[it] = fmaf(p.x, v0, fmaf(p.y, v1, fmaf(p.z, v2, fmaf(p.w, v3, oacc[it]))));
            }
        }
        #pragma unroll
        for (int it = 0; it < 8; it++) {
            int t = atw * 8 + it;
            if (t < TT)
                sm[AO_OFF + t * 132 + gb + lane] = oacc[it];
        }
    }
    __syncthreads();   // Vt and P now dead -> Wc tiles + PB overlay

    // ---- Y = O @ Wc^T + residual (fp32 f32x2, f-split + reduce) ----
    {
        load_wc2(sm, Wc, 0, tid);
        __syncthreads();

        u64 acc[8] = {0,0,0,0,0,0,0,0};
        const int wbase = AWC_OFF + fh * 4160;
        #pragma unroll 1
        for (int stage = 0; stage < 2; stage++) {
            const int fbase = fh * 64 + stage * 32;
            #pragma unroll 2
            for (int f4 = 0; f4 < 32; f4 += 4) {
                u64 w0 = *(const u64*)&sm[wbase + (f4 + 0) * 130 + gp];
                u64 w1 = *(const u64*)&sm[wbase + (f4 + 1) * 130 + gp];
                u64 w2 = *(const u64*)&sm[wbase + (f4 + 2) * 130 + gp];
                u64 w3 = *(const u64*)&sm[wbase + (f4 + 3) * 130 + gp];
                #pragma unroll
                for (int it = 0; it < 8; it++) {
                    int tr = ytw * 8 + it; tr = tr < TT ? tr : (TT - 1);
                    float4 a = *(const float4*)&sm[AO_OFF + tr * 132 + fbase + f4];
                    acc[it] = ffma2(dup2(a.x), w0, acc[it]);
                    acc[it] = ffma2(dup2(a.y), w1, acc[it]);
                    acc[it] = ffma2(dup2(a.z), w2, acc[it]);
                    acc[it] = ffma2(dup2(a.w), w3, acc[it]);
                }
            }
            if (stage == 0) {
                __syncthreads();
                load_wc2(sm, Wc, 1, tid);
                __syncthreads();
            }
        }
        // reduce f-halves: fh1 stores partial pairs, fh0 combines + residual
        if (fh == 1) {
            #pragma unroll
            for (int it = 0; it < 8; it++) {
                int t = ytw * 8 + it;
                if (t < TT)
                    *(u64*)&sm[APB_OFF + (t * 64 + lane + 32 * gsub) * 2] = acc[it];
            }
        }
        __syncthreads();
        if (fh == 0) {
            #pragma unroll
            for (int it = 0; it < 8; it++) {
                int t = ytw * 8 + it;
                if (t < TT) {
                    u64 part = *(const u64*)&sm[APB_OFF + (t * 64 + lane + 32 * gsub) * 2];
                    float2 v = unpack2(addf2(acc[it], part));
                    size_t o = (size_t)(t * NUNIT + bid) * FF + gp;
                    float2 xv = *(const float2*)&veh[o];
                    v.x += xv.x; v.y += xv.y;
                    *(float2*)&out[o] = v;
                }
            }
        }
    }
}

// ================= launcher =================
extern "C" void kernel_launch(void* const* d_in, const int* in_sizes, int n_in,
                              void* d_out, int out_size)
{
    const float* veh   = (const float*)d_in[0];
    const float* lanes = (const float*)d_in[1];
    const int*   maskl = (const int*)d_in[2];
    const float* Wk    = (const float*)d_in[3];
    const float* Wv    = (const float*)d_in[4];
    const float* Wq    = (const float*)d_in[5];
    const float* Wc    = (const float*)d_in[6];
    float* out = (float*)d_out;

    cudaFuncSetAttribute(proj_gemm, cudaFuncAttributeMaxDynamicSharedMemorySize, PROJ_SMEM);
    cudaFuncSetAttribute(attn_y_kernel, cudaFuncAttributeMaxDynamicSharedMemorySize,
                         A_SMEM_FLOATS * (int)sizeof(float));

    proj_gemm<<<PROJ_BLOCKS, 256, PROJ_SMEM>>>(lanes, Wk, Wv, veh, Wq);
    attn_y_kernel<<<NUNIT, 512, A_SMEM_FLOATS * sizeof(float)>>>(maskl, Wc, veh, out);
}

// round 15
// speedup vs baseline: 1.2773x; 1.2773x over previous
#include <cuda_runtime.h>
#include <cstdint>

// LaneAttention, sm_103: R13 structure (proj_gemm + attn + y_gemm) with
// de-duplicated mask reduction + vectorized staging in the attention kernel.

#define TT    30
#define FF    128
#define LL    64
#define LFN   64
#define THN   20
#define NUNIT 2048
#define NROWQ (TT*NUNIT)   // 61440

#define KV_BLOCKS (2 * 296)          // 592
#define Q_BLOCKS  (NROWQ / 128)      // 480
#define PROJ_BLOCKS (KV_BLOCKS + Q_BLOCKS)

typedef unsigned long long u64;

// ---------------- scratch ----------------
__device__ float g_K[NUNIT * 128 * 64];
__device__ float g_V[NUNIT * 128 * 64];
__device__ float g_Q[NROWQ * 128];
__device__ float g_O[NROWQ * 128];

// ---------------- tf32 helpers ----------------
__device__ __forceinline__ uint32_t to_tf32(float x) {
    uint32_t r;
    asm("cvt.rna.tf32.f32 %0, %1;" : "=r"(r) : "f"(x));
    return r;
}
__device__ __forceinline__ void mma_tf32(float* d, const uint32_t* a,
                                         uint32_t b0, uint32_t b1) {
    asm volatile(
        "mma.sync.aligned.m16n8k8.row.col.f32.tf32.tf32.f32 "
        "{%0,%1,%2,%3}, {%4,%5,%6,%7}, {%8,%9}, {%0,%1,%2,%3};"
        : "+f"(d[0]), "+f"(d[1]), "+f"(d[2]), "+f"(d[3])
        : "r"(a[0]), "r"(a[1]), "r"(a[2]), "r"(a[3]), "r"(b0), "r"(b1));
}
__device__ __forceinline__ uint32_t f2u(float x) { return __float_as_uint(x); }

__device__ __forceinline__ void stage64(float* hi, float* lo,
                                        const float* __restrict__ src,
                                        int ld, int tid)
{
    for (int i4 = tid; i4 < 128 * 16; i4 += 256) {
        int r = i4 >> 4, k = (i4 & 15) * 4;
        float4 v = *(const float4*)&src[(size_t)r * ld + k];
        uint32_t hx = to_tf32(v.x), hy = to_tf32(v.y),
                 hz = to_tf32(v.z), hw = to_tf32(v.w);
        int o = r * 68 + k;
        *(uint4*)&hi[o] = make_uint4(hx, hy, hz, hw);
        *(uint4*)&lo[o] = make_uint4(to_tf32(v.x - __uint_as_float(hx)),
                                     to_tf32(v.y - __uint_as_float(hy)),
                                     to_tf32(v.z - __uint_as_float(hz)),
                                     to_tf32(v.w - __uint_as_float(hw)));
    }
}
__device__ __forceinline__ void stage32(float* hi, float* lo,
                                        const float* __restrict__ src,
                                        int ld, int tid)
{
    for (int i4 = tid; i4 < 128 * 8; i4 += 256) {
        int r = i4 >> 3, k = (i4 & 7) * 4;
        float4 v = *(const float4*)&src[(size_t)r * ld + k];
        uint32_t hx = to_tf32(v.x), hy = to_tf32(v.y),
                 hz = to_tf32(v.z), hw = to_tf32(v.w);
        int o = r * 36 + k;
        *(uint4*)&hi[o] = make_uint4(hx, hy, hz, hw);
        *(uint4*)&lo[o] = make_uint4(to_tf32(v.x - __uint_as_float(hx)),
                                     to_tf32(v.y - __uint_as_float(hy)),
                                     to_tf32(v.z - __uint_as_float(hz)),
                                     to_tf32(v.w - __uint_as_float(hw)));
    }
}
__device__ __forceinline__ void prefetch32(float4 pf[4],
                                           const float* __restrict__ src,
                                           int ld, int tid)
{
    #pragma unroll
    for (int j = 0; j < 4; j++) {
        int i4 = tid + j * 256;
        int r = i4 >> 3, k = (i4 & 7) * 4;
        pf[j] = *(const float4*)&src[(size_t)r * ld + k];
    }
}
__device__ __forceinline__ void commit32(float* hi, float* lo,
                                         const float4 pf[4], int tid)
{
    #pragma unroll
    for (int j = 0; j < 4; j++) {
        int i4 = tid + j * 256;
        int r = i4 >> 3, k = (i4 & 7) * 4;
        float4 v = pf[j];
        uint32_t hx = to_tf32(v.x), hy = to_tf32(v.y),
                 hz = to_tf32(v.z), hw = to_tf32(v.w);
        int o = r * 36 + k;
        *(uint4*)&hi[o] = make_uint4(hx, hy, hz, hw);
        *(uint4*)&lo[o] = make_uint4(to_tf32(v.x - __uint_as_float(hx)),
                                     to_tf32(v.y - __uint_as_float(hy)),
                                     to_tf32(v.z - __uint_as_float(hz)),
                                     to_tf32(v.w - __uint_as_float(hw)));
    }
}

__device__ __forceinline__ void mma_k32(const float* aH, const float* aL, int lda,
                                        const float* bH, const float* bL, int ldb,
                                        float d[2][8][4],
                                        int wm, int wn, int qr, int qc)
{
    #pragma unroll 1
    for (int ks = 0; ks < 4; ks++) {
        const int kb = ks * 8 + qc;
        uint32_t ah[2][4], al[2][4];
        #pragma unroll
        for (int i = 0; i < 2; i++) {
            int r0 = (wm + i * 16 + qr) * lda;
            ah[i][0] = f2u(aH[r0 + kb]);
            ah[i][1] = f2u(aH[r0 + 8 * lda + kb]);
            ah[i][2] = f2u(aH[r0 + kb + 4]);
            ah[i][3] = f2u(aH[r0 + 8 * lda + kb + 4]);
            al[i][0] = f2u(aL[r0 + kb]);
            al[i][1] = f2u(aL[r0 + 8 * lda + kb]);
            al[i][2] = f2u(aL[r0 + kb + 4]);
            al[i][3] = f2u(aL[r0 + 8 * lda + kb + 4]);
        }
        #pragma unroll
        for (int j = 0; j < 8; j++) {
            int nb = (wn + j * 8 + qr) * ldb;
            uint32_t bh0 = f2u(bH[nb + kb]);
            uint32_t bh1 = f2u(bH[nb + kb + 4]);
            uint32_t bl0 = f2u(bL[nb + kb]);
            uint32_t bl1 = f2u(bL[nb + kb + 4]);
            #pragma unroll
            for (int i = 0; i < 2; i++) {
                mma_tf32(d[i][j], ah[i], bh0, bh1);
                mma_tf32(d[i][j], ah[i], bl0, bl1);
                mma_tf32(d[i][j], al[i], bh0, bh1);
            }
        }
    }
}

// ================= merged projection kernel (identical to R13) =================
#define PROJ_SMEM (26624 * 4)   // 106496 B -> 2 CTAs/SM

__global__ void __launch_bounds__(256, 2)
proj_gemm(const float* __restrict__ lanes, const float* __restrict__ Wk,
          const float* __restrict__ Wv, const float* __restrict__ veh,
          const float* __restrict__ Wq)
{
    extern __shared__ float sm[];
    const int tid = threadIdx.x, wid = tid >> 5, lane = tid & 31;
    const int qr = lane >> 2, qc = lane & 3;
    const int wm = (wid >> 1) * 32, wn = (wid & 1) * 64;

    if (blockIdx.x < KV_BLOCKS) {
        float* AH = sm;
        float* AL = sm + 8704;
        float* BH = sm + 17408;
        float* BL = sm + 22016;
        const int nt = blockIdx.x / 296, b2 = blockIdx.x % 296;

        stage64(AH, AL, nt ? Wv : Wk, 64, tid);
        float* dst = nt ? g_V : g_K;

        float4 pf[4];
        prefetch32(pf, lanes + (size_t)b2 * 8192, 64, tid);

        #pragma unroll 1
        for (int ntile = b2; ntile < 1024; ntile += 296) {
            float d[2][8][4];
            #pragma unroll
            for (int i = 0; i < 2; i++)
                #pragma unroll
                for (int j = 0; j < 8; j++)
                    d[i][j][0] = d[i][j][1] = d[i][j][2] = d[i][j][3] = 0.f;

            #pragma unroll 1
            for (int ch = 0; ch < 2; ch++) {
                __syncthreads();
                commit32(BH, BL, pf, tid);
                __syncthreads();
                if (ch == 0) {
                    prefetch32(pf, lanes + (size_t)ntile * 8192 + 32, 64, tid);
                } else if (ntile + 296 < 1024) {
                    prefetch32(pf, lanes + (size_t)(ntile + 296) * 8192, 64, tid);
                }
                mma_k32(AH + ch * 32, AL + ch * 32, 68, BH, BL, 36,
                        d, wm, wn, qr, qc);
            }

            const int u0 = ntile * 2;
            #pragma unroll
            for (int i = 0; i < 2; i++)
                #pragma unroll
                for (int j = 0; j < 8; j++) {
                    int g = wm + i * 16 + qr;
                    int c = wn + j * 8 + 2 * qc;
                    int u = u0 + (c >> 6), l = c & 63;
                    *(float2*)&dst[(size_t)u * 8192 + g * 64 + l] =
                        make_float2(d[i][j][0], d[i][j][1]);
                    *(float2*)&dst[(size_t)u * 8192 + (g + 8) * 64 + l] =
                        make_float2(d[i][j][2], d[i][j][3]);
                }
        }
    } else {
        float* AH = sm;
        float* AL = sm + 4608;
        float* BH = sm + 9216;
        float* BL = sm + 13824;
        const int m0 = (blockIdx.x - KV_BLOCKS) * 128;

        float d[2][8][4];
        #pragma unroll
        for (int i = 0; i < 2; i++)
            #pragma unroll
            for (int j = 0; j < 8; j++)
                d[i][j][0] = d[i][j][1] = d[i][j][2] = d[i][j][3] = 0.f;

        float4 pf[4];
        prefetch32(pf, veh + (size_t)m0 * 128, 128, tid);

        #pragma unroll 1
        for (int ch = 0; ch < 4; ch++) {
            commit32(AH, AL, pf, tid);
            stage32(BH, BL, Wq + ch * 32, 128, tid);
            __syncthreads();
            if (ch < 3)
                prefetch32(pf, veh + (size_t)m0 * 128 + (ch + 1) * 32, 128, tid);
            mma_k32(AH, AL, 36, BH, BL, 36, d, wm, wn, qr, qc);
            __syncthreads();
        }

        #pragma unroll
        for (int i = 0; i < 2; i++)
            #pragma unroll
            for (int j = 0; j < 8; j++) {
                int r = m0 + wm + i * 16 + qr, c = wn + j * 8 + 2 * qc;
                *(float2*)&g_Q[(size_t)r * 128 + c]       = make_float2(d[i][j][0], d[i][j][1]);
                *(float2*)&g_Q[(size_t)(r + 8) * 128 + c] = make_float2(d[i][j][2], d[i][j][3]);
            }
    }
}

// ================= Y GEMM (identical to R13) =================
#define QY_SMEM (18432 * 4)   // 73728 B

__global__ void __launch_bounds__(256, 2)
y_gemm(const float* __restrict__ Wc, const float* __restrict__ veh,
       float* __restrict__ out)
{
    extern __shared__ float sm[];
    float* AH = sm;
    float* AL = sm + 4608;
    float* BH = sm + 9216;
    float* BL = sm + 13824;
    const int tid = threadIdx.x, wid = tid >> 5, lane = tid & 31;
    const int qr = lane >> 2, qc = lane & 3;
    const int m0 = blockIdx.x * 128;
    const int wm = (wid >> 1) * 32, wn = (wid & 1) * 64;

    float d[2][8][4];
    #pragma unroll
    for (int i = 0; i < 2; i++)
        #pragma unroll
        for (int j = 0; j < 8; j++)
            d[i][j][0] = d[i][j][1] = d[i][j][2] = d[i][j][3] = 0.f;

    float4 pf[4];
    prefetch32(pf, g_O + (size_t)m0 * 128, 128, tid);

    #pragma unroll 1
    for (int ch = 0; ch < 4; ch++) {
        commit32(AH, AL, pf, tid);
        stage32(BH, BL, Wc + ch * 32, 128, tid);
        __syncthreads();
        if (ch < 3)
            prefetch32(pf, g_O + (size_t)m0 * 128 + (ch + 1) * 32, 128, tid);
        mma_k32(AH, AL, 36, BH, BL, 36, d, wm, wn, qr, qc);
        __syncthreads();
    }

    #pragma unroll
    for (int i = 0; i < 2; i++)
        #pragma unroll
        for (int j = 0; j < 8; j++) {
            int r = m0 + wm + i * 16 + qr, c = wn + j * 8 + 2 * qc;
            size_t o0 = (size_t)r * 128 + c, o1 = (size_t)(r + 8) * 128 + c;
            float2 x0 = *(const float2*)&veh[o0];
            float2 x1 = *(const float2*)&veh[o1];
            *(float2*)&out[o0] = make_float2(d[i][j][0] + x0.x, d[i][j][1] + x0.y);
            *(float2*)&out[o1] = make_float2(d[i][j][2] + x1.x, d[i][j][3] + x1.y);
        }
}

// ================= attention kernel (fp32, per-unit) =================
// SMEM floats: Kt[128][68] @0, Vt[128][65] @8704, Q[30][132] @17024,
//              P[30][256] @20984, mask[64] @28664. Total 28728 = 114912 B.
#define AKT_OFF 0
#define AVT_OFF 8704
#define AQ_OFF  17024
#define AP_OFF  20984
#define AMK_OFF 28664
#define A_SMEM_FLOATS 28728

__device__ __forceinline__ u64 ffma2(u64 a, u64 b, u64 c) {
    u64 d;
    asm("fma.rn.f32x2 %0, %1, %2, %3;" : "=l"(d) : "l"(a), "l"(b), "l"(c));
    return d;
}
__device__ __forceinline__ u64 dup2(float x) {
    u64 d; asm("mov.b64 %0, {%1, %1};" : "=l"(d) : "f"(x)); return d;
}
__device__ __forceinline__ u64 pack2(float lo, float hi) {
    u64 d; asm("mov.b64 %0, {%1, %2};" : "=l"(d) : "f"(lo), "f"(hi)); return d;
}
__device__ __forceinline__ float2 unpack2(u64 a) {
    float2 r; asm("mov.b64 {%0, %1}, %2;" : "=f"(r.x), "=f"(r.y) : "l"(a)); return r;
}

__global__ void __launch_bounds__(512, 2)
attn_kernel(const int* __restrict__ maskl)
{
    extern __shared__ float sm[];
    const int tid  = threadIdx.x;
    const int w    = tid >> 5;
    const int lane = tid & 31;
    const int bid  = blockIdx.x;
    const int ah   = w & 3;
    const int atw  = w >> 2;

    // ---- cooperative mask reduction (threads 0..63 only) ----
    if (tid < LL) {
        int m = 0;
        #pragma unroll
        for (int th = 0; th < THN; th++)
            m |= maskl[(size_t)(th * NUNIT + bid) * LL + tid];
        sm[AMK_OFF + tid] = m ? 1.0f : 0.0f;
    }

    // ---- vectorized staging of Kt (f4->f4), Vt (f4->4xf), Q (f4->f4) ----
    {
        const float* kp = g_K + (size_t)bid * 8192;
        const float* vp = g_V + (size_t)bid * 8192;
        for (int i4 = tid; i4 < 2048; i4 += 512) {
            int g = i4 >> 4, l = (i4 & 15) * 4;
            float4 kv = *(const float4*)&kp[g * 64 + l];
            *(float4*)&sm[AKT_OFF + g * 68 + l] = kv;
            float4 vv = *(const float4*)&vp[g * 64 + l];
            int vo = AVT_OFF + g * 65 + l;
            sm[vo + 0] = vv.x; sm[vo + 1] = vv.y;
            sm[vo + 2] = vv.z; sm[vo + 3] = vv.w;
        }
        for (int i4 = tid; i4 < TT * 32; i4 += 512) {
            int t = i4 >> 5, gq = (i4 & 31) * 4;
            float4 qv = *(const float4*)&g_Q[(size_t)(t * NUNIT + bid) * 128 + gq];
            *(float4*)&sm[AQ_OFF + t * 132 + gq] = qv;
        }
    }
    __syncthreads();

    const bool km0 = sm[AMK_OFF + lane] > 0.f;
    const bool km1 = sm[AMK_OFF + lane + 32] > 0.f;

    // ---- scores + softmax -> P ----
    {
        const int gb = ah * 32;
        u64 acc[8] = {0,0,0,0,0,0,0,0};
        #pragma unroll 2
        for (int d = 0; d < 32; d += 4) {
            u64 kk[4];
            #pragma unroll
            for (int j = 0; j < 4; j++) {
                float k0 = sm[AKT_OFF + (gb + d + j) * 68 + lane];
                float k1 = sm[AKT_OFF + (gb + d + j) * 68 + lane + 32];
                kk[j] = pack2(k0, k1);
            }
            #pragma unroll
            for (int it = 0; it < 8; it++) {
                int tr = atw * 8 + it; tr = tr < TT ? tr : (TT - 1);
                float4 q = *(const float4*)&sm[AQ_OFF + tr * 132 + gb + d];
                acc[it] = ffma2(dup2(q.x), kk[0], acc[it]);
                acc[it] = ffma2(dup2(q.y), kk[1], acc[it]);
                acc[it] = ffma2(dup2(q.z), kk[2], acc[it]);
                acc[it] = ffma2(dup2(q.w), kk[3], acc[it]);
            }
        }
        const float scale = 0.17677669529663687f;
        #pragma unroll
        for (int it = 0; it < 8; it++) {
            int t = atw * 8 + it;
            if (t >= TT) break;
            float2 sc = unpack2(acc[it]);
            float s0 = km0 ? sc.x * scale : -1e9f;
            float s1 = km1 ? sc.y * scale : -1e9f;
            float m = fmaxf(s0, s1);
            #pragma unroll
            for (int o = 16; o; o >>= 1) m = fmaxf(m, __shfl_xor_sync(0xffffffffu, m, o));
            float e0 = __expf(s0 - m), e1 = __expf(s1 - m);
            float ss = e0 + e1;
            #pragma unroll
            for (int o = 16; o; o >>= 1) ss += __shfl_xor_sync(0xffffffffu, ss, o);
            float inv = 1.0f / ss;
            sm[AP_OFF + t * 256 + ah * 64 + lane]      = e0 * inv;
            sm[AP_OFF + t * 256 + ah * 64 + lane + 32] = e1 * inv;
        }
    }
    __syncthreads();

    // ---- O = P @ V -> g_O ----
    {
        const int gb = ah * 32;
        const int vrow = AVT_OFF + (gb + lane) * 65;
        float oacc[8] = {0,0,0,0,0,0,0,0};
        #pragma unroll 2
        for (int l = 0; l < LL; l += 4) {
            float v0 = sm[vrow + l + 0];
            float v1 = sm[vrow + l + 1];
            float v2 = sm[vrow + l + 2];
            float v3 = sm[vrow + l + 3];
            #pragma unroll
            for (int it = 0; it < 8; it++) {
                int tr = atw * 8 + it; tr = tr < TT ? tr : (TT - 1);
                float4 p = *(const float4*)&sm[AP_OFF + tr * 256 + ah * 64 + l];
                oacc[it] = fmaf(p.x, v0, fmaf(p.y, v1, fmaf(p.z, v2, fmaf(p.w, v3, oacc[it]))));
            }
        }
        #pragma unroll
        for (int it = 0; it < 8; it++) {
            int t = atw * 8 + it;
            if (t < TT)
                g_O[(size_t)(t * NUNIT + bid) * 128 + gb + lane] = oacc[it];
        }
    }
}

// ================= launcher =================
extern "C" void kernel_launch(void* const* d_in, const int* in_sizes, int n_in,
                              void* d_out, int out_size)
{
    const float* veh   = (const float*)d_in[0];
    const float* lanes = (const float*)d_in[1];
    const int*   maskl = (const int*)d_in[2];
    const float* Wk    = (const float*)d_in[3];
    const float* Wv    = (const float*)d_in[4];
    const float* Wq    = (const float*)d_in[5];
    const float* Wc    = (const float*)d_in[6];
    float* out = (float*)d_out;

    cudaFuncSetAttribute(proj_gemm, cudaFuncAttributeMaxDynamicSharedMemorySize, PROJ_SMEM);
    cudaFuncSetAttribute(y_gemm,   cudaFuncAttributeMaxDynamicSharedMemorySize, QY_SMEM);
    cudaFuncSetAttribute(attn_kernel, cudaFuncAttributeMaxDynamicSharedMemorySize,
                         A_SMEM_FLOATS * (int)sizeof(float));

    proj_gemm<<<PROJ_BLOCKS, 256, PROJ_SMEM>>>(lanes, Wk, Wv, veh, Wq);
    attn_kernel<<<NUNIT, 512, A_SMEM_FLOATS * sizeof(float)>>>(maskl);
    y_gemm<<<Q_BLOCKS, 256, QY_SMEM>>>(Wc, veh, out);
}